// round 8
// baseline (speedup 1.0000x reference)
#include <cuda_runtime.h>
#include <cuda_bf16.h>
#include <cstdint>

// ---- problem constants ----
#define B_    8
#define N1_   8192
#define N2_   2048
#define C1_   128
#define C2_   256
#define O1_   256
#define O2_   256

// ---- device scratch ----
__device__ __align__(16) __nv_bfloat16 g_W1a_hi[O1_ * C2_], g_W1a_lo[O1_ * C2_];
__device__ __align__(16) __nv_bfloat16 g_W1b_hi[O1_ * C1_], g_W1b_lo[O1_ * C1_];
__device__ __align__(16) __nv_bfloat16 g_W2_hi [O2_ * O1_], g_W2_lo [O2_ * O1_];
__device__ float g_b1eff[O1_], g_b2eff[O2_];
__device__ __align__(16) __nv_bfloat16 g_f1T_hi[(size_t)B_ * N1_ * C1_], g_f1T_lo[(size_t)B_ * N1_ * C1_];
__device__ __align__(16) __nv_bfloat16 g_f2T_hi[(size_t)B_ * N2_ * C2_], g_f2T_lo[(size_t)B_ * N2_ * C2_];
__device__ __align__(16) float g_PT[(size_t)B_ * N2_ * O1_];      // P^T [b][n2][o1]
__device__ __align__(16) float4 g_xyz2p[B_ * N2_];                // packed (x,y,z,|q|^2)
__device__ int   g_idx[B_ * N1_ * 3];
__device__ float g_wgt[B_ * N1_ * 3];

// ============================================================
// portable tensor-core primitives
// ============================================================
__device__ __forceinline__ uint32_t smem_u32(const void* p) {
    uint32_t a;
    asm("{ .reg .u64 t; cvta.to.shared.u64 t, %1; cvt.u32.u64 %0, t; }" : "=r"(a) : "l"(p));
    return a;
}
__device__ __forceinline__ void ldsm4(uint32_t* r, uint32_t addr) {
    asm volatile("ldmatrix.sync.aligned.m8n8.x4.shared.b16 {%0,%1,%2,%3}, [%4];"
                 : "=r"(r[0]), "=r"(r[1]), "=r"(r[2]), "=r"(r[3]) : "r"(addr));
}
__device__ __forceinline__ void mma16816(float* c, const uint32_t* a, uint32_t b0, uint32_t b1) {
    asm volatile(
        "mma.sync.aligned.m16n8k16.row.col.f32.bf16.bf16.f32 "
        "{%0,%1,%2,%3}, {%4,%5,%6,%7}, {%8,%9}, {%0,%1,%2,%3};"
        : "+f"(c[0]), "+f"(c[1]), "+f"(c[2]), "+f"(c[3])
        : "r"(a[0]), "r"(a[1]), "r"(a[2]), "r"(a[3]), "r"(b0), "r"(b1));
}
__device__ __forceinline__ uint32_t splitpack(float a, float b, uint32_t& lo) {
    __nv_bfloat16 ha = __float2bfloat16(a), hb = __float2bfloat16(b);
    __nv_bfloat16 la = __float2bfloat16(a - __bfloat162float(ha));
    __nv_bfloat16 lb = __float2bfloat16(b - __bfloat162float(hb));
    __nv_bfloat162 H2; H2.x = ha; H2.y = hb;
    __nv_bfloat162 L2; L2.x = la; L2.y = lb;
    lo = *(uint32_t*)&L2;
    return *(uint32_t*)&H2;
}

// ============================================================
// FUSED gemm1+gemm2. Per CTA: 64 points x full O1=256.
// 256 threads = 8 warps (2M x 4N), warp tile 32(M) x 64(N).
// smem 106KB -> 2 CTAs/SM. A-staging and outT alias the h1 region.
// ============================================================
#define FSLD 40      // staging pitch (bf16 el)
#define H1P  264     // h1 smem pitch (bf16 el)
#define OTP  68      // out-tile pitch (fp32 el)
#define OF_H1HI 0
#define OF_H1LO 33792
#define OF_AHI  0            // stage-1 A staging (aliases h1hi; dead before h1 written)
#define OF_ALO  5120
#define OF_BHI  67584        // B staging hi (20480B)
#define OF_BLO  88064        // B staging lo (20480B)
#define OF_OUTT 0            // out tile (aliases h1 + head of B staging; both dead)
#define FSM_BYTES 108544

__global__ void __launch_bounds__(256, 2) fused12_kernel(float* __restrict__ out) {
    extern __shared__ __align__(16) char fsm[];
    __nv_bfloat16* h1hi = (__nv_bfloat16*)(fsm + OF_H1HI);
    __nv_bfloat16* h1lo = (__nv_bfloat16*)(fsm + OF_H1LO);
    float*         outT = (float*)(fsm + OF_OUTT);
    __nv_bfloat16* sAhi = (__nv_bfloat16*)(fsm + OF_AHI);
    __nv_bfloat16* sAlo = (__nv_bfloat16*)(fsm + OF_ALO);
    __nv_bfloat16* sBhi = (__nv_bfloat16*)(fsm + OF_BHI);
    __nv_bfloat16* sBlo = (__nv_bfloat16*)(fsm + OF_BLO);

    const int tid = threadIdx.x, lane = tid & 31, wid = tid >> 5;
    const int warpM = wid >> 2, warpN = wid & 3;      // 2 x 4
    const int b = blockIdx.y;
    const int pt0 = blockIdx.x * 64;

    const uint32_t h1hiB = smem_u32(h1hi), h1loB = smem_u32(h1lo);
    const uint32_t sAhiB = smem_u32(sAhi), sAloB = smem_u32(sAlo);
    const uint32_t sBhiB = smem_u32(sBhi), sBloB = smem_u32(sBlo);

    const int lrow = tid >> 2;          // 0..63
    const int lcol = (tid & 3) * 8;     // 0,8,16,24

    const uint32_t aRowSel = lane & 15;
    const uint32_t aColSel = (lane >> 4) << 3;
    const uint32_t bRow = ((lane >> 4) << 3) + (lane & 7);
    const uint32_t bCol = ((lane >> 3) & 1) << 3;

    // ---------------- stage 1: h1 = f1T @ W1b^T  (K=128, 4 chunks) ----------------
    const __nv_bfloat16* Ah = g_f1T_hi + ((size_t)b * N1_ + pt0 + lrow) * C1_ + lcol;
    const __nv_bfloat16* Al = g_f1T_lo + ((size_t)b * N1_ + pt0 + lrow) * C1_ + lcol;
    const __nv_bfloat16* B1h = g_W1b_hi + (size_t)lrow * C1_ + lcol;
    const __nv_bfloat16* B1l = g_W1b_lo + (size_t)lrow * C1_ + lcol;

    float acc[2][8][4];
    #pragma unroll
    for (int i = 0; i < 2; i++)
        #pragma unroll
        for (int j = 0; j < 8; j++)
            #pragma unroll
            for (int k = 0; k < 4; k++) acc[i][j][k] = 0.f;

    uint4 rA0, rA1, rBh[4], rBl[4];
    rA0 = *(const uint4*)Ah;
    rA1 = *(const uint4*)Al;
    #pragma unroll
    for (int r = 0; r < 4; r++) {
        rBh[r] = *(const uint4*)(B1h + (size_t)r * 64 * C1_);
        rBl[r] = *(const uint4*)(B1l + (size_t)r * 64 * C1_);
    }

    for (int kb = 0; kb < C1_; kb += 32) {
        *(uint4*)&sAhi[lrow * FSLD + lcol] = rA0;
        *(uint4*)&sAlo[lrow * FSLD + lcol] = rA1;
        #pragma unroll
        for (int r = 0; r < 4; r++) {
            *(uint4*)&sBhi[(lrow + r * 64) * FSLD + lcol] = rBh[r];
            *(uint4*)&sBlo[(lrow + r * 64) * FSLD + lcol] = rBl[r];
        }
        __syncthreads();

        int nk = (kb + 32 < C1_) ? kb + 32 : 0;
        rA0 = *(const uint4*)(Ah + nk);
        rA1 = *(const uint4*)(Al + nk);
        #pragma unroll
        for (int r = 0; r < 4; r++) {
            rBh[r] = *(const uint4*)(B1h + (size_t)r * 64 * C1_ + nk);
            rBl[r] = *(const uint4*)(B1l + (size_t)r * 64 * C1_ + nk);
        }

        #pragma unroll
        for (int ks = 0; ks < 2; ks++) {
            uint32_t ah[2][4], al[2][4];
            #pragma unroll
            for (int mi = 0; mi < 2; mi++) {
                uint32_t off = ((warpM * 32 + mi * 16 + aRowSel) * FSLD + ks * 16 + aColSel) * 2;
                ldsm4(ah[mi], sAhiB + off);
                ldsm4(al[mi], sAloB + off);
            }
            #pragma unroll
            for (int nj = 0; nj < 4; nj++) {
                uint32_t bh[4], bl[4];
                uint32_t off = ((warpN * 64 + nj * 16 + bRow) * FSLD + ks * 16 + bCol) * 2;
                ldsm4(bh, sBhiB + off);
                ldsm4(bl, sBloB + off);
                #pragma unroll
                for (int mi = 0; mi < 2; mi++)
                    #pragma unroll
                    for (int sub = 0; sub < 2; sub++) {
                        int ni = nj * 2 + sub;
                        uint32_t b0 = bh[sub * 2], b1 = bh[sub * 2 + 1];
                        uint32_t c0_ = bl[sub * 2], c1_ = bl[sub * 2 + 1];
                        mma16816(acc[mi][ni], ah[mi], b0, b1);
                        mma16816(acc[mi][ni], ah[mi], c0_, c1_);
                        mma16816(acc[mi][ni], al[mi], b0, b1);
                    }
            }
        }
        __syncthreads();
    }

    // prefetch stage-2 W2 chunk 0 during gather epilogue
    const __nv_bfloat16* B2h = g_W2_hi + (size_t)lrow * O1_ + lcol;
    const __nv_bfloat16* B2l = g_W2_lo + (size_t)lrow * O1_ + lcol;
    #pragma unroll
    for (int r = 0; r < 4; r++) {
        rBh[r] = *(const uint4*)(B2h + (size_t)r * 64 * O1_);
        rBl[r] = *(const uint4*)(B2l + (size_t)r * 64 * O1_);
    }

    // ---------------- epilogue 1: gather + bias + relu -> h1 smem ----------------
    {
        const int r0 = lane >> 2;
        const int c0 = (lane & 3) * 2;
        const int*   IX = g_idx + (size_t)b * N1_ * 3;
        const float* WG = g_wgt + (size_t)b * N1_ * 3;
        const float* PT = g_PT + (size_t)b * N2_ * O1_;
        #pragma unroll
        for (int mi = 0; mi < 2; mi++)
            #pragma unroll
            for (int h = 0; h < 2; h++) {
                int gmL = warpM * 32 + mi * 16 + r0 + h * 8;    // 0..63
                int n = pt0 + gmL;
                int i0 = IX[n * 3], i1 = IX[n * 3 + 1], i2 = IX[n * 3 + 2];
                float w0 = WG[n * 3], w1 = WG[n * 3 + 1], w2 = WG[n * 3 + 2];
                #pragma unroll
                for (int ni = 0; ni < 8; ni++) {
                    int gn = warpN * 64 + ni * 8 + c0;
                    float2 p0 = *(const float2*)&PT[(size_t)i0 * O1_ + gn];
                    float2 p1 = *(const float2*)&PT[(size_t)i1 * O1_ + gn];
                    float2 p2 = *(const float2*)&PT[(size_t)i2 * O1_ + gn];
                    float2 bs = *(const float2*)&g_b1eff[gn];
                    float v0 = acc[mi][ni][h * 2 + 0] + bs.x + w0 * p0.x + w1 * p1.x + w2 * p2.x;
                    float v1 = acc[mi][ni][h * 2 + 1] + bs.y + w0 * p0.y + w1 * p1.y + w2 * p2.y;
                    v0 = fmaxf(v0, 0.f); v1 = fmaxf(v1, 0.f);
                    uint32_t lo, hi = splitpack(v0, v1, lo);
                    *(uint32_t*)&h1hi[gmL * H1P + gn] = hi;
                    *(uint32_t*)&h1lo[gmL * H1P + gn] = lo;
                }
            }
    }
    __syncthreads();

    // ---------------- stage 2: out = relu(h1 @ W2^T + b2)  (K=256, 8 chunks) ----------------
    float acc2[2][8][4];
    #pragma unroll
    for (int i = 0; i < 2; i++)
        #pragma unroll
        for (int j = 0; j < 8; j++)
            #pragma unroll
            for (int k = 0; k < 4; k++) acc2[i][j][k] = 0.f;

    for (int kb = 0; kb < O1_; kb += 32) {
        #pragma unroll
        for (int r = 0; r < 4; r++) {
            *(uint4*)&sBhi[(lrow + r * 64) * FSLD + lcol] = rBh[r];
            *(uint4*)&sBlo[(lrow + r * 64) * FSLD + lcol] = rBl[r];
        }
        __syncthreads();

        int nk = (kb + 32 < O1_) ? kb + 32 : 0;
        #pragma unroll
        for (int r = 0; r < 4; r++) {
            rBh[r] = *(const uint4*)(B2h + (size_t)r * 64 * O1_ + nk);
            rBl[r] = *(const uint4*)(B2l + (size_t)r * 64 * O1_ + nk);
        }

        #pragma unroll
        for (int ks = 0; ks < 2; ks++) {
            uint32_t ah[2][4], al[2][4];
            #pragma unroll
            for (int mi = 0; mi < 2; mi++) {
                uint32_t off = ((warpM * 32 + mi * 16 + aRowSel) * H1P + kb + ks * 16 + aColSel) * 2;
                ldsm4(ah[mi], h1hiB + off);
                ldsm4(al[mi], h1loB + off);
            }
            #pragma unroll
            for (int nj = 0; nj < 4; nj++) {
                uint32_t bh[4], bl[4];
                uint32_t off = ((warpN * 64 + nj * 16 + bRow) * FSLD + ks * 16 + bCol) * 2;
                ldsm4(bh, sBhiB + off);
                ldsm4(bl, sBloB + off);
                #pragma unroll
                for (int mi = 0; mi < 2; mi++)
                    #pragma unroll
                    for (int sub = 0; sub < 2; sub++) {
                        int ni = nj * 2 + sub;
                        uint32_t b0 = bh[sub * 2], b1 = bh[sub * 2 + 1];
                        uint32_t c0_ = bl[sub * 2], c1_ = bl[sub * 2 + 1];
                        mma16816(acc2[mi][ni], ah[mi], b0, b1);
                        mma16816(acc2[mi][ni], ah[mi], c0_, c1_);
                        mma16816(acc2[mi][ni], al[mi], b0, b1);
                    }
            }
        }
        __syncthreads();
    }

    // ---------------- epilogue 2: transpose via smem, coalesced store ----------------
    {
        const int r0 = lane >> 2;
        const int c0 = (lane & 3) * 2;
        #pragma unroll
        for (int mi = 0; mi < 2; mi++)
            #pragma unroll
            for (int h = 0; h < 2; h++) {
                int gmL = warpM * 32 + mi * 16 + r0 + h * 8;
                #pragma unroll
                for (int ni = 0; ni < 8; ni++) {
                    int gn = warpN * 64 + ni * 8 + c0;
                    float2 bs = *(const float2*)&g_b2eff[gn];
                    outT[(size_t)gn * OTP + gmL]       = fmaxf(acc2[mi][ni][h * 2 + 0] + bs.x, 0.f);
                    outT[(size_t)(gn + 1) * OTP + gmL] = fmaxf(acc2[mi][ni][h * 2 + 1] + bs.y, 0.f);
                }
            }
    }
    __syncthreads();

    float* dst = out + (size_t)b * O2_ * N1_ + pt0;
    for (int i = tid; i < 256 * 16; i += 256) {
        int o2 = i >> 4;
        int c = (i & 15) << 2;
        uint4 v = *(uint4*)&outT[o2 * OTP + c];
        *(uint4*)(dst + (size_t)o2 * N1_ + c) = v;
    }
}

// ============================================================
// gemmP: PT[b][n2][o1] = (f2T @ W1a^T)  (verified core, unchanged)
// ============================================================
__global__ void __launch_bounds__(256, 2) gemmP_kernel() {
    __shared__ __align__(16) __nv_bfloat16 sAhi[64][FSLD],  sAlo[64][FSLD];
    __shared__ __align__(16) __nv_bfloat16 sBhi[128][FSLD], sBlo[128][FSLD];

    const int tid = threadIdx.x, lane = tid & 31, wid = tid >> 5;
    const int warpM = wid >> 2, warpN = wid & 3;
    const int b = blockIdx.z;
    const int Mbase = blockIdx.x * 64, Nbase = blockIdx.y * 128;

    float acc[2][4][4];
    #pragma unroll
    for (int i = 0; i < 2; i++)
        #pragma unroll
        for (int j = 0; j < 4; j++)
            #pragma unroll
            for (int k = 0; k < 4; k++) acc[i][j][k] = 0.f;

    const int lrow = tid >> 2;
    const int lcol = (tid & 3) * 8;

    const __nv_bfloat16* pAhi = g_f2T_hi + ((size_t)b * N2_ + Mbase + lrow) * C2_ + lcol;
    const __nv_bfloat16* pAlo = g_f2T_lo + ((size_t)b * N2_ + Mbase + lrow) * C2_ + lcol;
    const __nv_bfloat16* pBhi0 = g_W1a_hi + (size_t)(Nbase + lrow) * C2_ + lcol;
    const __nv_bfloat16* pBlo0 = g_W1a_lo + (size_t)(Nbase + lrow) * C2_ + lcol;
    const __nv_bfloat16* pBhi1 = g_W1a_hi + (size_t)(Nbase + lrow + 64) * C2_ + lcol;
    const __nv_bfloat16* pBlo1 = g_W1a_lo + (size_t)(Nbase + lrow + 64) * C2_ + lcol;

    const uint32_t aRowA = warpM * 32 + (lane & 15);
    const uint32_t aColA = (lane >> 4) << 3;
    const uint32_t bRowB = warpN * 32 + ((lane >> 4) << 3) + (lane & 7);
    const uint32_t bColB = ((lane >> 3) & 1) << 3;
    const uint32_t sAhiB = smem_u32(&sAhi[0][0]), sAloB = smem_u32(&sAlo[0][0]);
    const uint32_t sBhiB = smem_u32(&sBhi[0][0]), sBloB = smem_u32(&sBlo[0][0]);

    uint4 rA0 = *(const uint4*)pAhi,  rA1 = *(const uint4*)pAlo;
    uint4 rBh0 = *(const uint4*)pBhi0, rBh1 = *(const uint4*)pBhi1;
    uint4 rBl0 = *(const uint4*)pBlo0, rBl1 = *(const uint4*)pBlo1;

    for (int kb = 0; kb < C2_; kb += 32) {
        *(uint4*)&sAhi[lrow][lcol] = rA0;
        *(uint4*)&sAlo[lrow][lcol] = rA1;
        *(uint4*)&sBhi[lrow][lcol] = rBh0;
        *(uint4*)&sBhi[lrow + 64][lcol] = rBh1;
        *(uint4*)&sBlo[lrow][lcol] = rBl0;
        *(uint4*)&sBlo[lrow + 64][lcol] = rBl1;
        __syncthreads();

        int nk = (kb + 32 < C2_) ? kb + 32 : 0;
        rA0 = *(const uint4*)(pAhi + nk);  rA1 = *(const uint4*)(pAlo + nk);
        rBh0 = *(const uint4*)(pBhi0 + nk); rBh1 = *(const uint4*)(pBhi1 + nk);
        rBl0 = *(const uint4*)(pBlo0 + nk); rBl1 = *(const uint4*)(pBlo1 + nk);

        #pragma unroll
        for (int ks = 0; ks < 2; ks++) {
            uint32_t ah[2][4], al[2][4], bh[2][4], bl[2][4];
            #pragma unroll
            for (int mi = 0; mi < 2; mi++) {
                uint32_t off = ((aRowA + mi * 16) * FSLD + ks * 16 + aColA) * 2;
                ldsm4(ah[mi], sAhiB + off);
                ldsm4(al[mi], sAloB + off);
            }
            #pragma unroll
            for (int nj = 0; nj < 2; nj++) {
                uint32_t off = ((bRowB + nj * 16) * FSLD + ks * 16 + bColB) * 2;
                ldsm4(bh[nj], sBhiB + off);
                ldsm4(bl[nj], sBloB + off);
            }
            #pragma unroll
            for (int mi = 0; mi < 2; mi++)
                #pragma unroll
                for (int ni = 0; ni < 4; ni++) {
                    const uint32_t* BH = bh[ni >> 1];
                    const uint32_t* BL = bl[ni >> 1];
                    uint32_t b0 = BH[(ni & 1) * 2], b1 = BH[(ni & 1) * 2 + 1];
                    uint32_t c0_ = BL[(ni & 1) * 2], c1_ = BL[(ni & 1) * 2 + 1];
                    mma16816(acc[mi][ni], ah[mi], b0, b1);
                    mma16816(acc[mi][ni], ah[mi], c0_, c1_);
                    mma16816(acc[mi][ni], al[mi], b0, b1);
                }
        }
        __syncthreads();
    }

    const int r0 = lane >> 2;
    const int c0 = (lane & 3) * 2;
    float* outP = g_PT + (size_t)b * N2_ * O1_;
    #pragma unroll
    for (int mi = 0; mi < 2; mi++)
        #pragma unroll
        for (int h = 0; h < 2; h++) {
            int gm = Mbase + warpM * 32 + mi * 16 + r0 + h * 8;
            #pragma unroll
            for (int ni = 0; ni < 4; ni++) {
                int gn = Nbase + warpN * 32 + ni * 8 + c0;
                *(float2*)&outP[(size_t)gm * O1_ + gn] =
                    make_float2(acc[mi][ni][h * 2], acc[mi][ni][h * 2 + 1]);
            }
        }
}

// ============================================================
// prep: fold BN into W/b, split weights, pack xyz2 -> float4
// ============================================================
__global__ void prep_kernel(const float* __restrict__ W1, const float* __restrict__ b1,
                            const float* __restrict__ g1, const float* __restrict__ be1,
                            const float* __restrict__ W2, const float* __restrict__ b2,
                            const float* __restrict__ g2, const float* __restrict__ be2,
                            const float* __restrict__ xyz2) {
    const float rs = 0.99999500003749969f;  // 1/sqrt(1+1e-5)
    int t = blockIdx.x * blockDim.x + threadIdx.x;
    int nt = gridDim.x * blockDim.x;
    for (int i = t; i < O1_ * C2_; i += nt) {
        int o = i / C2_;
        float w = W1[o * (C1_ + C2_) + (i % C2_)] * g1[o] * rs;
        __nv_bfloat16 hi = __float2bfloat16(w);
        g_W1a_hi[i] = hi;
        g_W1a_lo[i] = __float2bfloat16(w - __bfloat162float(hi));
    }
    for (int i = t; i < O1_ * C1_; i += nt) {
        int o = i / C1_;
        float w = W1[o * (C1_ + C2_) + C2_ + (i % C1_)] * g1[o] * rs;
        __nv_bfloat16 hi = __float2bfloat16(w);
        g_W1b_hi[i] = hi;
        g_W1b_lo[i] = __float2bfloat16(w - __bfloat162float(hi));
    }
    for (int i = t; i < O2_ * O1_; i += nt) {
        int o = i / O1_;
        float w = W2[i] * g2[o] * rs;
        __nv_bfloat16 hi = __float2bfloat16(w);
        g_W2_hi[i] = hi;
        g_W2_lo[i] = __float2bfloat16(w - __bfloat162float(hi));
    }
    for (int i = t; i < O1_; i += nt) g_b1eff[i] = g1[i] * rs * b1[i] + be1[i];
    for (int i = t; i < O2_; i += nt) g_b2eff[i] = g2[i] * rs * b2[i] + be2[i];
    for (int i = t; i < B_ * N2_; i += nt) {
        float ax = xyz2[i * 3 + 0], ay = xyz2[i * 3 + 1], az = xyz2[i * 3 + 2];
        g_xyz2p[i] = make_float4(ax, ay, az, ax * ax + ay * ay + az * az);
    }
}

// ============================================================
// COMBO: knn (smem-free, L1-broadcast reads) + tsplit1 + tsplit2
// ============================================================
#define KNN_BLKS  (N1_ / 512 * B_)                    // 128
#define TS1_BLKS  ((N1_ / 32) * (C1_ / 32) * B_)      // 8192
#define TS2_BLKS  ((N2_ / 32) * (C2_ / 32) * B_)      // 4096

__device__ __forceinline__ void knn3_insert(float dd, int m,
                                            float& d0, float& d1, float& d2,
                                            int& j0, int& j1, int& j2) {
    if (dd < d2) {
        if (dd < d1) {
            d2 = d1; j2 = j1;
            if (dd < d0) { d1 = d0; j1 = j0; d0 = dd; j0 = m; }
            else         { d1 = dd; j1 = m; }
        } else { d2 = dd; j2 = m; }
    }
}

__device__ void knn_body(int px, int b, const float* __restrict__ xyz1) {
    const float4* __restrict__ s2 = g_xyz2p + (size_t)b * N2_;

    int pA = px * 512 + threadIdx.x;
    int pB = pA + 256;
    const float* ppA = xyz1 + ((size_t)b * N1_ + pA) * 3;
    const float* ppB = xyz1 + ((size_t)b * N1_ + pB) * 3;
    float xA = ppA[0], yA = ppA[1], zA = ppA[2];
    float xB = ppB[0], yB = ppB[1], zB = ppB[2];
    float p2A = xA * xA + yA * yA + zA * zA;
    float p2B = xB * xB + yB * yB + zB * zB;

    float dA0 = 3.4e38f, dA1 = 3.4e38f, dA2 = 3.4e38f;
    float dB0 = 3.4e38f, dB1 = 3.4e38f, dB2 = 3.4e38f;
    int jA0 = 0, jA1 = 0, jA2 = 0, jB0 = 0, jB1 = 0, jB2 = 0;
    #pragma unroll 4
    for (int m = 0; m < N2_; m++) {
        float4 v = __ldg(&s2[m]);     // uniform per warp -> L1 broadcast
        float ddA = (p2A + v.w) - 2.0f * (xA * v.x + yA * v.y + zA * v.z);
        float ddB = (p2B + v.w) - 2.0f * (xB * v.x + yB * v.y + zB * v.z);
        knn3_insert(ddA, m, dA0, dA1, dA2, jA0, jA1, jA2);
        knn3_insert(ddB, m, dB0, dB1, dB2, jB0, jB1, jB2);
    }
    #pragma unroll
    for (int s = 0; s < 2; s++) {
        float d0 = s ? dB0 : dA0, d1 = s ? dB1 : dA1, d2 = s ? dB2 : dA2;
        int   j0 = s ? jB0 : jA0, j1 = s ? jB1 : jA1, j2 = s ? jB2 : jA2;
        int   p  = s ? pB : pA;
        float w0 = 1.0f / fmaxf(sqrtf(fmaxf(d0, 0.f)), 1e-8f);
        float w1 = 1.0f / fmaxf(sqrtf(fmaxf(d1, 0.f)), 1e-8f);
        float w2 = 1.0f / fmaxf(sqrtf(fmaxf(d2, 0.f)), 1e-8f);
        float inv = 1.0f / (w0 + w1 + w2);
        size_t base = ((size_t)b * N1_ + p) * 3;
        g_idx[base + 0] = j0; g_idx[base + 1] = j1; g_idx[base + 2] = j2;
        g_wgt[base + 0] = w0 * inv; g_wgt[base + 1] = w1 * inv; g_wgt[base + 2] = w2 * inv;
    }
}

__device__ void tsplit_tile(int n_t, int c_t, int b,
                            const float* __restrict__ src,
                            __nv_bfloat16* __restrict__ dhi,
                            __nv_bfloat16* __restrict__ dlo,
                            int C, int Np, float (*t)[33]) {
    int n0 = n_t * 32, c0 = c_t * 32;
    int tx = threadIdx.x & 31, ty = threadIdx.x >> 5;
    #pragma unroll
    for (int r = 0; r < 4; r++) {
        int c = c0 + ty + r * 8;
        t[ty + r * 8][tx] = src[((size_t)b * C + c) * Np + n0 + tx];
    }
    __syncthreads();
    #pragma unroll
    for (int r = 0; r < 4; r++) {
        int n = n0 + ty + r * 8;
        int c = c0 + tx;
        float v = t[tx][ty + r * 8];
        __nv_bfloat16 hi = __float2bfloat16(v);
        size_t o = ((size_t)b * Np + n) * C + c;
        dhi[o] = hi;
        dlo[o] = __float2bfloat16(v - __bfloat162float(hi));
    }
}

__global__ void __launch_bounds__(256) combo_kernel(const float* __restrict__ xyz1,
                                                    const float* __restrict__ feats1,
                                                    const float* __restrict__ feats2) {
    __shared__ float t[32][33];       // 4.2KB only
    int bid = blockIdx.x;
    if (bid < KNN_BLKS) {
        knn_body(bid & (N1_ / 512 - 1), bid >> 4, xyz1);
        return;
    }
    bid -= KNN_BLKS;
    if (bid < TS1_BLKS) {
        int n_t = bid & 255, c_t = (bid >> 8) & 3, b = bid >> 10;
        tsplit_tile(n_t, c_t, b, feats1, g_f1T_hi, g_f1T_lo, C1_, N1_, t);
        return;
    }
    bid -= TS1_BLKS;
    {
        int n_t = bid & 63, c_t = (bid >> 6) & 7, b = bid >> 9;
        tsplit_tile(n_t, c_t, b, feats2, g_f2T_hi, g_f2T_lo, C2_, N2_, t);
    }
}

// ============================================================
extern "C" void kernel_launch(void* const* d_in, const int* in_sizes, int n_in,
                              void* d_out, int out_size) {
    const float* xyz1   = (const float*)d_in[0];
    const float* xyz2   = (const float*)d_in[1];
    const float* feats1 = (const float*)d_in[2];
    const float* feats2 = (const float*)d_in[3];
    const float* W1     = (const float*)d_in[4];
    const float* b1     = (const float*)d_in[5];
    const float* g1     = (const float*)d_in[6];
    const float* be1    = (const float*)d_in[7];
    const float* W2     = (const float*)d_in[8];
    const float* b2     = (const float*)d_in[9];
    const float* g2     = (const float*)d_in[10];
    const float* be2    = (const float*)d_in[11];
    float* out = (float*)d_out;

    cudaFuncSetAttribute(fused12_kernel, cudaFuncAttributeMaxDynamicSharedMemorySize, FSM_BYTES);

    prep_kernel<<<64, 256>>>(W1, b1, g1, be1, W2, b2, g2, be2, xyz2);            // idx 0
    combo_kernel<<<KNN_BLKS + TS1_BLKS + TS2_BLKS, 256>>>(xyz1, feats1, feats2); // idx 1
    gemmP_kernel<<<dim3(N2_ / 64, O1_ / 128, B_), 256>>>();                      // idx 2
    fused12_kernel<<<dim3(N1_ / 64, B_), 256, FSM_BYTES>>>(out);                 // idx 3 -> ncu
}

// round 9
// speedup vs baseline: 1.7174x; 1.7174x over previous
#include <cuda_runtime.h>
#include <cuda_bf16.h>
#include <cstdint>

// ---- problem constants ----
#define B_    8
#define N1_   8192
#define N2_   2048
#define C1_   128
#define C2_   256
#define O1_   256
#define O2_   256

// ---- device scratch ----
__device__ __align__(16) __nv_bfloat16 g_W1a_hi[O1_ * C2_], g_W1a_lo[O1_ * C2_];
__device__ __align__(16) __nv_bfloat16 g_W1b_hi[O1_ * C1_], g_W1b_lo[O1_ * C1_];
__device__ __align__(16) __nv_bfloat16 g_W2_hi [O2_ * O1_], g_W2_lo [O2_ * O1_];
__device__ float g_b1eff[O1_], g_b2eff[O2_];
__device__ __align__(16) __nv_bfloat16 g_f1T_hi[(size_t)B_ * N1_ * C1_], g_f1T_lo[(size_t)B_ * N1_ * C1_];
__device__ __align__(16) __nv_bfloat16 g_f2T_hi[(size_t)B_ * N2_ * C2_], g_f2T_lo[(size_t)B_ * N2_ * C2_];
__device__ __align__(16) float g_PT[(size_t)B_ * N2_ * O1_];      // P^T [b][n2][o1]
__device__ int   g_idx[B_ * N1_ * 3];
__device__ float g_wgt[B_ * N1_ * 3];

// ============================================================
// portable tensor-core primitives
// ============================================================
__device__ __forceinline__ uint32_t smem_u32(const void* p) {
    uint32_t a;
    asm("{ .reg .u64 t; cvta.to.shared.u64 t, %1; cvt.u32.u64 %0, t; }" : "=r"(a) : "l"(p));
    return a;
}
__device__ __forceinline__ void ldsm4(uint32_t* r, uint32_t addr) {
    asm volatile("ldmatrix.sync.aligned.m8n8.x4.shared.b16 {%0,%1,%2,%3}, [%4];"
                 : "=r"(r[0]), "=r"(r[1]), "=r"(r[2]), "=r"(r[3]) : "r"(addr));
}
__device__ __forceinline__ void mma16816(float* c, const uint32_t* a, uint32_t b0, uint32_t b1) {
    asm volatile(
        "mma.sync.aligned.m16n8k16.row.col.f32.bf16.bf16.f32 "
        "{%0,%1,%2,%3}, {%4,%5,%6,%7}, {%8,%9}, {%0,%1,%2,%3};"
        : "+f"(c[0]), "+f"(c[1]), "+f"(c[2]), "+f"(c[3])
        : "r"(a[0]), "r"(a[1]), "r"(a[2]), "r"(a[3]), "r"(b0), "r"(b1));
}
__device__ __forceinline__ uint32_t splitpack(float a, float b, uint32_t& lo) {
    __nv_bfloat16 ha = __float2bfloat16(a), hb = __float2bfloat16(b);
    __nv_bfloat16 la = __float2bfloat16(a - __bfloat162float(ha));
    __nv_bfloat16 lb = __float2bfloat16(b - __bfloat162float(hb));
    __nv_bfloat162 H2; H2.x = ha; H2.y = hb;
    __nv_bfloat162 L2; L2.x = la; L2.y = lb;
    lo = *(uint32_t*)&L2;
    return *(uint32_t*)&H2;
}

// ============================================================
// FUSED gemm1+gemm2 (exactly the R8-measured 172us version).
// Per CTA: 64 points x full O1=256. 256 threads = 8 warps (2M x 4N).
// ============================================================
#define FSLD 40
#define H1P  264
#define OTP  68
#define OF_H1HI 0
#define OF_H1LO 33792
#define OF_AHI  0
#define OF_ALO  5120
#define OF_BHI  67584
#define OF_BLO  88064
#define OF_OUTT 0
#define FSM_BYTES 108544

__global__ void __launch_bounds__(256, 2) fused12_kernel(float* __restrict__ out) {
    extern __shared__ __align__(16) char fsm[];
    __nv_bfloat16* h1hi = (__nv_bfloat16*)(fsm + OF_H1HI);
    __nv_bfloat16* h1lo = (__nv_bfloat16*)(fsm + OF_H1LO);
    float*         outT = (float*)(fsm + OF_OUTT);
    __nv_bfloat16* sAhi = (__nv_bfloat16*)(fsm + OF_AHI);
    __nv_bfloat16* sAlo = (__nv_bfloat16*)(fsm + OF_ALO);
    __nv_bfloat16* sBhi = (__nv_bfloat16*)(fsm + OF_BHI);
    __nv_bfloat16* sBlo = (__nv_bfloat16*)(fsm + OF_BLO);

    const int tid = threadIdx.x, lane = tid & 31, wid = tid >> 5;
    const int warpM = wid >> 2, warpN = wid & 3;
    const int b = blockIdx.y;
    const int pt0 = blockIdx.x * 64;

    const uint32_t h1hiB = smem_u32(h1hi), h1loB = smem_u32(h1lo);
    const uint32_t sAhiB = smem_u32(sAhi), sAloB = smem_u32(sAlo);
    const uint32_t sBhiB = smem_u32(sBhi), sBloB = smem_u32(sBlo);

    const int lrow = tid >> 2;
    const int lcol = (tid & 3) * 8;

    const uint32_t aRowSel = lane & 15;
    const uint32_t aColSel = (lane >> 4) << 3;
    const uint32_t bRow = ((lane >> 4) << 3) + (lane & 7);
    const uint32_t bCol = ((lane >> 3) & 1) << 3;

    // ---------------- stage 1: h1 = f1T @ W1b^T  (K=128) ----------------
    const __nv_bfloat16* Ah = g_f1T_hi + ((size_t)b * N1_ + pt0 + lrow) * C1_ + lcol;
    const __nv_bfloat16* Al = g_f1T_lo + ((size_t)b * N1_ + pt0 + lrow) * C1_ + lcol;
    const __nv_bfloat16* B1h = g_W1b_hi + (size_t)lrow * C1_ + lcol;
    const __nv_bfloat16* B1l = g_W1b_lo + (size_t)lrow * C1_ + lcol;

    float acc[2][8][4];
    #pragma unroll
    for (int i = 0; i < 2; i++)
        #pragma unroll
        for (int j = 0; j < 8; j++)
            #pragma unroll
            for (int k = 0; k < 4; k++) acc[i][j][k] = 0.f;

    uint4 rA0, rA1, rBh[4], rBl[4];
    rA0 = *(const uint4*)Ah;
    rA1 = *(const uint4*)Al;
    #pragma unroll
    for (int r = 0; r < 4; r++) {
        rBh[r] = *(const uint4*)(B1h + (size_t)r * 64 * C1_);
        rBl[r] = *(const uint4*)(B1l + (size_t)r * 64 * C1_);
    }

    for (int kb = 0; kb < C1_; kb += 32) {
        *(uint4*)&sAhi[lrow * FSLD + lcol] = rA0;
        *(uint4*)&sAlo[lrow * FSLD + lcol] = rA1;
        #pragma unroll
        for (int r = 0; r < 4; r++) {
            *(uint4*)&sBhi[(lrow + r * 64) * FSLD + lcol] = rBh[r];
            *(uint4*)&sBlo[(lrow + r * 64) * FSLD + lcol] = rBl[r];
        }
        __syncthreads();

        int nk = (kb + 32 < C1_) ? kb + 32 : 0;
        rA0 = *(const uint4*)(Ah + nk);
        rA1 = *(const uint4*)(Al + nk);
        #pragma unroll
        for (int r = 0; r < 4; r++) {
            rBh[r] = *(const uint4*)(B1h + (size_t)r * 64 * C1_ + nk);
            rBl[r] = *(const uint4*)(B1l + (size_t)r * 64 * C1_ + nk);
        }

        #pragma unroll
        for (int ks = 0; ks < 2; ks++) {
            uint32_t ah[2][4], al[2][4];
            #pragma unroll
            for (int mi = 0; mi < 2; mi++) {
                uint32_t off = ((warpM * 32 + mi * 16 + aRowSel) * FSLD + ks * 16 + aColSel) * 2;
                ldsm4(ah[mi], sAhiB + off);
                ldsm4(al[mi], sAloB + off);
            }
            #pragma unroll
            for (int nj = 0; nj < 4; nj++) {
                uint32_t bh[4], bl[4];
                uint32_t off = ((warpN * 64 + nj * 16 + bRow) * FSLD + ks * 16 + bCol) * 2;
                ldsm4(bh, sBhiB + off);
                ldsm4(bl, sBloB + off);
                #pragma unroll
                for (int mi = 0; mi < 2; mi++)
                    #pragma unroll
                    for (int sub = 0; sub < 2; sub++) {
                        int ni = nj * 2 + sub;
                        uint32_t b0 = bh[sub * 2], b1 = bh[sub * 2 + 1];
                        uint32_t c0_ = bl[sub * 2], c1_ = bl[sub * 2 + 1];
                        mma16816(acc[mi][ni], ah[mi], b0, b1);
                        mma16816(acc[mi][ni], ah[mi], c0_, c1_);
                        mma16816(acc[mi][ni], al[mi], b0, b1);
                    }
            }
        }
        __syncthreads();
    }

    const __nv_bfloat16* B2h = g_W2_hi + (size_t)lrow * O1_ + lcol;
    const __nv_bfloat16* B2l = g_W2_lo + (size_t)lrow * O1_ + lcol;
    #pragma unroll
    for (int r = 0; r < 4; r++) {
        rBh[r] = *(const uint4*)(B2h + (size_t)r * 64 * O1_);
        rBl[r] = *(const uint4*)(B2l + (size_t)r * 64 * O1_);
    }

    // ---------------- epilogue 1: gather + bias + relu -> h1 smem ----------------
    {
        const int r0 = lane >> 2;
        const int c0 = (lane & 3) * 2;
        const int*   IX = g_idx + (size_t)b * N1_ * 3;
        const float* WG = g_wgt + (size_t)b * N1_ * 3;
        const float* PT = g_PT + (size_t)b * N2_ * O1_;
        #pragma unroll
        for (int mi = 0; mi < 2; mi++)
            #pragma unroll
            for (int h = 0; h < 2; h++) {
                int gmL = warpM * 32 + mi * 16 + r0 + h * 8;
                int n = pt0 + gmL;
                int i0 = IX[n * 3], i1 = IX[n * 3 + 1], i2 = IX[n * 3 + 2];
                float w0 = WG[n * 3], w1 = WG[n * 3 + 1], w2 = WG[n * 3 + 2];
                #pragma unroll
                for (int ni = 0; ni < 8; ni++) {
                    int gn = warpN * 64 + ni * 8 + c0;
                    float2 p0 = *(const float2*)&PT[(size_t)i0 * O1_ + gn];
                    float2 p1 = *(const float2*)&PT[(size_t)i1 * O1_ + gn];
                    float2 p2 = *(const float2*)&PT[(size_t)i2 * O1_ + gn];
                    float2 bs = *(const float2*)&g_b1eff[gn];
                    float v0 = acc[mi][ni][h * 2 + 0] + bs.x + w0 * p0.x + w1 * p1.x + w2 * p2.x;
                    float v1 = acc[mi][ni][h * 2 + 1] + bs.y + w0 * p0.y + w1 * p1.y + w2 * p2.y;
                    v0 = fmaxf(v0, 0.f); v1 = fmaxf(v1, 0.f);
                    uint32_t lo, hi = splitpack(v0, v1, lo);
                    *(uint32_t*)&h1hi[gmL * H1P + gn] = hi;
                    *(uint32_t*)&h1lo[gmL * H1P + gn] = lo;
                }
            }
    }
    __syncthreads();

    // ---------------- stage 2: out = relu(h1 @ W2^T + b2)  (K=256) ----------------
    float acc2[2][8][4];
    #pragma unroll
    for (int i = 0; i < 2; i++)
        #pragma unroll
        for (int j = 0; j < 8; j++)
            #pragma unroll
            for (int k = 0; k < 4; k++) acc2[i][j][k] = 0.f;

    for (int kb = 0; kb < O1_; kb += 32) {
        #pragma unroll
        for (int r = 0; r < 4; r++) {
            *(uint4*)&sBhi[(lrow + r * 64) * FSLD + lcol] = rBh[r];
            *(uint4*)&sBlo[(lrow + r * 64) * FSLD + lcol] = rBl[r];
        }
        __syncthreads();

        int nk = (kb + 32 < O1_) ? kb + 32 : 0;
        #pragma unroll
        for (int r = 0; r < 4; r++) {
            rBh[r] = *(const uint4*)(B2h + (size_t)r * 64 * O1_ + nk);
            rBl[r] = *(const uint4*)(B2l + (size_t)r * 64 * O1_ + nk);
        }

        #pragma unroll
        for (int ks = 0; ks < 2; ks++) {
            uint32_t ah[2][4], al[2][4];
            #pragma unroll
            for (int mi = 0; mi < 2; mi++) {
                uint32_t off = ((warpM * 32 + mi * 16 + aRowSel) * H1P + kb + ks * 16 + aColSel) * 2;
                ldsm4(ah[mi], h1hiB + off);
                ldsm4(al[mi], h1loB + off);
            }
            #pragma unroll
            for (int nj = 0; nj < 4; nj++) {
                uint32_t bh[4], bl[4];
                uint32_t off = ((warpN * 64 + nj * 16 + bRow) * FSLD + ks * 16 + bCol) * 2;
                ldsm4(bh, sBhiB + off);
                ldsm4(bl, sBloB + off);
                #pragma unroll
                for (int mi = 0; mi < 2; mi++)
                    #pragma unroll
                    for (int sub = 0; sub < 2; sub++) {
                        int ni = nj * 2 + sub;
                        uint32_t b0 = bh[sub * 2], b1 = bh[sub * 2 + 1];
                        uint32_t c0_ = bl[sub * 2], c1_ = bl[sub * 2 + 1];
                        mma16816(acc2[mi][ni], ah[mi], b0, b1);
                        mma16816(acc2[mi][ni], ah[mi], c0_, c1_);
                        mma16816(acc2[mi][ni], al[mi], b0, b1);
                    }
            }
        }
        __syncthreads();
    }

    // ---------------- epilogue 2 ----------------
    {
        const int r0 = lane >> 2;
        const int c0 = (lane & 3) * 2;
        #pragma unroll
        for (int mi = 0; mi < 2; mi++)
            #pragma unroll
            for (int h = 0; h < 2; h++) {
                int gmL = warpM * 32 + mi * 16 + r0 + h * 8;
                #pragma unroll
                for (int ni = 0; ni < 8; ni++) {
                    int gn = warpN * 64 + ni * 8 + c0;
                    float2 bs = *(const float2*)&g_b2eff[gn];
                    outT[(size_t)gn * OTP + gmL]       = fmaxf(acc2[mi][ni][h * 2 + 0] + bs.x, 0.f);
                    outT[(size_t)(gn + 1) * OTP + gmL] = fmaxf(acc2[mi][ni][h * 2 + 1] + bs.y, 0.f);
                }
            }
    }
    __syncthreads();

    float* dst = out + (size_t)b * O2_ * N1_ + pt0;
    for (int i = tid; i < 256 * 16; i += 256) {
        int o2 = i >> 4;
        int c = (i & 15) << 2;
        uint4 v = *(uint4*)&outT[o2 * OTP + c];
        *(uint4*)(dst + (size_t)o2 * N1_ + c) = v;
    }
}

// ============================================================
// gemmP: PT[b][n2][o1] = (f2T @ W1a^T)   (verified core, unchanged)
// ============================================================
__global__ void __launch_bounds__(256, 2) gemmP_kernel() {
    __shared__ __align__(16) __nv_bfloat16 sAhi[64][FSLD],  sAlo[64][FSLD];
    __shared__ __align__(16) __nv_bfloat16 sBhi[128][FSLD], sBlo[128][FSLD];

    const int tid = threadIdx.x, lane = tid & 31, wid = tid >> 5;
    const int warpM = wid >> 2, warpN = wid & 3;
    const int b = blockIdx.z;
    const int Mbase = blockIdx.x * 64, Nbase = blockIdx.y * 128;

    float acc[2][4][4];
    #pragma unroll
    for (int i = 0; i < 2; i++)
        #pragma unroll
        for (int j = 0; j < 4; j++)
            #pragma unroll
            for (int k = 0; k < 4; k++) acc[i][j][k] = 0.f;

    const int lrow = tid >> 2;
    const int lcol = (tid & 3) * 8;

    const __nv_bfloat16* pAhi = g_f2T_hi + ((size_t)b * N2_ + Mbase + lrow) * C2_ + lcol;
    const __nv_bfloat16* pAlo = g_f2T_lo + ((size_t)b * N2_ + Mbase + lrow) * C2_ + lcol;
    const __nv_bfloat16* pBhi0 = g_W1a_hi + (size_t)(Nbase + lrow) * C2_ + lcol;
    const __nv_bfloat16* pBlo0 = g_W1a_lo + (size_t)(Nbase + lrow) * C2_ + lcol;
    const __nv_bfloat16* pBhi1 = g_W1a_hi + (size_t)(Nbase + lrow + 64) * C2_ + lcol;
    const __nv_bfloat16* pBlo1 = g_W1a_lo + (size_t)(Nbase + lrow + 64) * C2_ + lcol;

    const uint32_t aRowA = warpM * 32 + (lane & 15);
    const uint32_t aColA = (lane >> 4) << 3;
    const uint32_t bRowB = warpN * 32 + ((lane >> 4) << 3) + (lane & 7);
    const uint32_t bColB = ((lane >> 3) & 1) << 3;
    const uint32_t sAhiB = smem_u32(&sAhi[0][0]), sAloB = smem_u32(&sAlo[0][0]);
    const uint32_t sBhiB = smem_u32(&sBhi[0][0]), sBloB = smem_u32(&sBlo[0][0]);

    uint4 rA0 = *(const uint4*)pAhi,  rA1 = *(const uint4*)pAlo;
    uint4 rBh0 = *(const uint4*)pBhi0, rBh1 = *(const uint4*)pBhi1;
    uint4 rBl0 = *(const uint4*)pBlo0, rBl1 = *(const uint4*)pBlo1;

    for (int kb = 0; kb < C2_; kb += 32) {
        *(uint4*)&sAhi[lrow][lcol] = rA0;
        *(uint4*)&sAlo[lrow][lcol] = rA1;
        *(uint4*)&sBhi[lrow][lcol] = rBh0;
        *(uint4*)&sBhi[lrow + 64][lcol] = rBh1;
        *(uint4*)&sBlo[lrow][lcol] = rBl0;
        *(uint4*)&sBlo[lrow + 64][lcol] = rBl1;
        __syncthreads();

        int nk = (kb + 32 < C2_) ? kb + 32 : 0;
        rA0 = *(const uint4*)(pAhi + nk);  rA1 = *(const uint4*)(pAlo + nk);
        rBh0 = *(const uint4*)(pBhi0 + nk); rBh1 = *(const uint4*)(pBhi1 + nk);
        rBl0 = *(const uint4*)(pBlo0 + nk); rBl1 = *(const uint4*)(pBlo1 + nk);

        #pragma unroll
        for (int ks = 0; ks < 2; ks++) {
            uint32_t ah[2][4], al[2][4], bh[2][4], bl[2][4];
            #pragma unroll
            for (int mi = 0; mi < 2; mi++) {
                uint32_t off = ((aRowA + mi * 16) * FSLD + ks * 16 + aColA) * 2;
                ldsm4(ah[mi], sAhiB + off);
                ldsm4(al[mi], sAloB + off);
            }
            #pragma unroll
            for (int nj = 0; nj < 2; nj++) {
                uint32_t off = ((bRowB + nj * 16) * FSLD + ks * 16 + bColB) * 2;
                ldsm4(bh[nj], sBhiB + off);
                ldsm4(bl[nj], sBloB + off);
            }
            #pragma unroll
            for (int mi = 0; mi < 2; mi++)
                #pragma unroll
                for (int ni = 0; ni < 4; ni++) {
                    const uint32_t* BH = bh[ni >> 1];
                    const uint32_t* BL = bl[ni >> 1];
                    uint32_t b0 = BH[(ni & 1) * 2], b1 = BH[(ni & 1) * 2 + 1];
                    uint32_t c0_ = BL[(ni & 1) * 2], c1_ = BL[(ni & 1) * 2 + 1];
                    mma16816(acc[mi][ni], ah[mi], b0, b1);
                    mma16816(acc[mi][ni], ah[mi], c0_, c1_);
                    mma16816(acc[mi][ni], al[mi], b0, b1);
                }
        }
        __syncthreads();
    }

    const int r0 = lane >> 2;
    const int c0 = (lane & 3) * 2;
    float* outP = g_PT + (size_t)b * N2_ * O1_;
    #pragma unroll
    for (int mi = 0; mi < 2; mi++)
        #pragma unroll
        for (int h = 0; h < 2; h++) {
            int gm = Mbase + warpM * 32 + mi * 16 + r0 + h * 8;
            #pragma unroll
            for (int ni = 0; ni < 4; ni++) {
                int gn = Nbase + warpN * 32 + ni * 8 + c0;
                *(float2*)&outP[(size_t)gm * O1_ + gn] =
                    make_float2(acc[mi][ni][h * 2], acc[mi][ni][h * 2 + 1]);
            }
        }
}

// ============================================================
// prep: fold BN into W/b, split weights into bf16 hi/lo
// ============================================================
__global__ void prep_kernel(const float* __restrict__ W1, const float* __restrict__ b1,
                            const float* __restrict__ g1, const float* __restrict__ be1,
                            const float* __restrict__ W2, const float* __restrict__ b2,
                            const float* __restrict__ g2, const float* __restrict__ be2) {
    const float rs = 0.99999500003749969f;  // 1/sqrt(1+1e-5)
    int t = blockIdx.x * blockDim.x + threadIdx.x;
    int nt = gridDim.x * blockDim.x;
    for (int i = t; i < O1_ * C2_; i += nt) {
        int o = i / C2_;
        float w = W1[o * (C1_ + C2_) + (i % C2_)] * g1[o] * rs;
        __nv_bfloat16 hi = __float2bfloat16(w);
        g_W1a_hi[i] = hi;
        g_W1a_lo[i] = __float2bfloat16(w - __bfloat162float(hi));
    }
    for (int i = t; i < O1_ * C1_; i += nt) {
        int o = i / C1_;
        float w = W1[o * (C1_ + C2_) + C2_ + (i % C1_)] * g1[o] * rs;
        __nv_bfloat16 hi = __float2bfloat16(w);
        g_W1b_hi[i] = hi;
        g_W1b_lo[i] = __float2bfloat16(w - __bfloat162float(hi));
    }
    for (int i = t; i < O2_ * O1_; i += nt) {
        int o = i / O1_;
        float w = W2[i] * g2[o] * rs;
        __nv_bfloat16 hi = __float2bfloat16(w);
        g_W2_hi[i] = hi;
        g_W2_lo[i] = __float2bfloat16(w - __bfloat162float(hi));
    }
    for (int i = t; i < O1_; i += nt) g_b1eff[i] = g1[i] * rs * b1[i] + be1[i];
    for (int i = t; i < O2_; i += nt) g_b2eff[i] = g2[i] * rs * b2[i] + be2[i];
}

// ============================================================
// kNN: R6-proven smem float4 version (1 point/thread)
// ============================================================
__global__ void __launch_bounds__(256) knn_kernel(const float* __restrict__ xyz1,
                                                  const float* __restrict__ xyz2) {
    __shared__ __align__(16) float4 s2[N2_];
    int b = blockIdx.y;
    const float* q = xyz2 + (size_t)b * N2_ * 3;
    for (int i = threadIdx.x; i < N2_; i += 256) {
        float ax = q[i * 3 + 0], ay = q[i * 3 + 1], az = q[i * 3 + 2];
        s2[i] = make_float4(ax, ay, az, ax * ax + ay * ay + az * az);
    }
    __syncthreads();

    int p = blockIdx.x * 256 + threadIdx.x;
    const float* pp = xyz1 + ((size_t)b * N1_ + p) * 3;
    float x = pp[0], y = pp[1], z = pp[2];
    float p2 = x * x + y * y + z * z;

    float d0 = 3.4e38f, d1 = 3.4e38f, d2 = 3.4e38f;
    int   j0 = 0, j1 = 0, j2 = 0;
    #pragma unroll 4
    for (int m = 0; m < N2_; m++) {
        float4 v = s2[m];
        float dot = x * v.x + y * v.y + z * v.z;
        float dd  = (p2 + v.w) - 2.0f * dot;
        if (dd < d2) {
            if (dd < d1) {
                d2 = d1; j2 = j1;
                if (dd < d0) { d1 = d0; j1 = j0; d0 = dd; j0 = m; }
                else         { d1 = dd; j1 = m; }
            } else { d2 = dd; j2 = m; }
        }
    }
    float r0 = sqrtf(fmaxf(d0, 0.f));
    float r1 = sqrtf(fmaxf(d1, 0.f));
    float r2 = sqrtf(fmaxf(d2, 0.f));
    float w0 = 1.0f / fmaxf(r0, 1e-8f);
    float w1 = 1.0f / fmaxf(r1, 1e-8f);
    float w2 = 1.0f / fmaxf(r2, 1e-8f);
    float inv = 1.0f / (w0 + w1 + w2);

    size_t base = ((size_t)b * N1_ + p) * 3;
    g_idx[base + 0] = j0; g_idx[base + 1] = j1; g_idx[base + 2] = j2;
    g_wgt[base + 0] = w0 * inv; g_wgt[base + 1] = w1 * inv; g_wgt[base + 2] = w2 * inv;
}

// ============================================================
// tsplit_both: transpose + split feats1 AND feats2, one kernel,
// only 4.2KB smem (R6 occupancy).
// ============================================================
#define TS1_BLKS  ((N1_ / 32) * (C1_ / 32) * B_)      // 8192
#define TS2_BLKS  ((N2_ / 32) * (C2_ / 32) * B_)      // 4096

__device__ __forceinline__ void tsplit_tile(int n_t, int c_t, int b,
                                            const float* __restrict__ src,
                                            __nv_bfloat16* __restrict__ dhi,
                                            __nv_bfloat16* __restrict__ dlo,
                                            int C, int Np, float (*t)[33]) {
    int n0 = n_t * 32, c0 = c_t * 32;
    int tx = threadIdx.x & 31, ty = threadIdx.x >> 5;
    #pragma unroll
    for (int r = 0; r < 4; r++) {
        int c = c0 + ty + r * 8;
        t[ty + r * 8][tx] = src[((size_t)b * C + c) * Np + n0 + tx];
    }
    __syncthreads();
    #pragma unroll
    for (int r = 0; r < 4; r++) {
        int n = n0 + ty + r * 8;
        int c = c0 + tx;
        float v = t[tx][ty + r * 8];
        __nv_bfloat16 hi = __float2bfloat16(v);
        size_t o = ((size_t)b * Np + n) * C + c;
        dhi[o] = hi;
        dlo[o] = __float2bfloat16(v - __bfloat162float(hi));
    }
}

__global__ void __launch_bounds__(256) tsplit_kernel(const float* __restrict__ feats1,
                                                     const float* __restrict__ feats2) {
    __shared__ float t[32][33];
    int bid = blockIdx.x;
    if (bid < TS1_BLKS) {
        int n_t = bid & 255, c_t = (bid >> 8) & 3, b = bid >> 10;
        tsplit_tile(n_t, c_t, b, feats1, g_f1T_hi, g_f1T_lo, C1_, N1_, t);
    } else {
        bid -= TS1_BLKS;
        int n_t = bid & 63, c_t = (bid >> 6) & 7, b = bid >> 9;
        tsplit_tile(n_t, c_t, b, feats2, g_f2T_hi, g_f2T_lo, C2_, N2_, t);
    }
}

// ============================================================
extern "C" void kernel_launch(void* const* d_in, const int* in_sizes, int n_in,
                              void* d_out, int out_size) {
    const float* xyz1   = (const float*)d_in[0];
    const float* xyz2   = (const float*)d_in[1];
    const float* feats1 = (const float*)d_in[2];
    const float* feats2 = (const float*)d_in[3];
    const float* W1     = (const float*)d_in[4];
    const float* b1     = (const float*)d_in[5];
    const float* g1     = (const float*)d_in[6];
    const float* be1    = (const float*)d_in[7];
    const float* W2     = (const float*)d_in[8];
    const float* b2     = (const float*)d_in[9];
    const float* g2     = (const float*)d_in[10];
    const float* be2    = (const float*)d_in[11];
    float* out = (float*)d_out;

    cudaFuncSetAttribute(fused12_kernel, cudaFuncAttributeMaxDynamicSharedMemorySize, FSM_BYTES);

    prep_kernel<<<64, 256>>>(W1, b1, g1, be1, W2, b2, g2, be2);       // idx 0
    knn_kernel<<<dim3(N1_ / 256, B_), 256>>>(xyz1, xyz2);             // idx 1
    tsplit_kernel<<<TS1_BLKS + TS2_BLKS, 256>>>(feats1, feats2);      // idx 2
    gemmP_kernel<<<dim3(N2_ / 64, O1_ / 128, B_), 256>>>();           // idx 3 -> ncu
    fused12_kernel<<<dim3(N1_ / 64, B_), 256, FSM_BYTES>>>(out);      // idx 4
}

// round 10
// speedup vs baseline: 2.0399x; 1.1878x over previous
#include <cuda_runtime.h>
#include <cuda_bf16.h>
#include <cstdint>

// ---- problem constants ----
#define B_    8
#define N1_   8192
#define N2_   2048
#define C1_   128
#define C2_   256
#define O1_   256
#define O2_   256

// ---- device scratch ----
__device__ __align__(16) __nv_bfloat16 g_W1a_hi[O1_ * C2_], g_W1a_lo[O1_ * C2_];
__device__ __align__(16) __nv_bfloat16 g_W1b_hi[O1_ * C1_], g_W1b_lo[O1_ * C1_];
__device__ __align__(16) __nv_bfloat16 g_W2_hi [O2_ * O1_], g_W2_lo [O2_ * O1_];
__device__ float g_b1eff[O1_], g_b2eff[O2_];
__device__ __align__(16) __nv_bfloat16 g_f1T_hi[(size_t)B_ * N1_ * C1_], g_f1T_lo[(size_t)B_ * N1_ * C1_];
__device__ __align__(16) __nv_bfloat16 g_f2T_hi[(size_t)B_ * N2_ * C2_], g_f2T_lo[(size_t)B_ * N2_ * C2_];
__device__ __align__(16) float g_PT[(size_t)B_ * N2_ * O1_];      // P^T [b][n2][o1]
__device__ int   g_idx[B_ * N1_ * 3];
__device__ float g_wgt[B_ * N1_ * 3];

// fragment-order packed weights: [kc][ks][warpN][nj][lane] -> uint4 (4 regs)
// W2:  kc 0..7 (K=256), W1b: kc 0..3 (K=128); warpN 0..3, nj 0..3, lane 0..31
__device__ __align__(16) uint4 g_W2p_hi [8 * 2 * 4 * 4 * 32];
__device__ __align__(16) uint4 g_W2p_lo [8 * 2 * 4 * 4 * 32];
__device__ __align__(16) uint4 g_W1bp_hi[4 * 2 * 4 * 4 * 32];
__device__ __align__(16) uint4 g_W1bp_lo[4 * 2 * 4 * 4 * 32];

// ============================================================
// portable tensor-core primitives
// ============================================================
__device__ __forceinline__ uint32_t smem_u32(const void* p) {
    uint32_t a;
    asm("{ .reg .u64 t; cvta.to.shared.u64 t, %1; cvt.u32.u64 %0, t; }" : "=r"(a) : "l"(p));
    return a;
}
__device__ __forceinline__ void ldsm4(uint32_t* r, uint32_t addr) {
    asm volatile("ldmatrix.sync.aligned.m8n8.x4.shared.b16 {%0,%1,%2,%3}, [%4];"
                 : "=r"(r[0]), "=r"(r[1]), "=r"(r[2]), "=r"(r[3]) : "r"(addr));
}
__device__ __forceinline__ void mma16816(float* c, const uint32_t* a, uint32_t b0, uint32_t b1) {
    asm volatile(
        "mma.sync.aligned.m16n8k16.row.col.f32.bf16.bf16.f32 "
        "{%0,%1,%2,%3}, {%4,%5,%6,%7}, {%8,%9}, {%0,%1,%2,%3};"
        : "+f"(c[0]), "+f"(c[1]), "+f"(c[2]), "+f"(c[3])
        : "r"(a[0]), "r"(a[1]), "r"(a[2]), "r"(a[3]), "r"(b0), "r"(b1));
}
__device__ __forceinline__ uint32_t splitpack(float a, float b, uint32_t& lo) {
    __nv_bfloat16 ha = __float2bfloat16(a), hb = __float2bfloat16(b);
    __nv_bfloat16 la = __float2bfloat16(a - __bfloat162float(ha));
    __nv_bfloat16 lb = __float2bfloat16(b - __bfloat162float(hb));
    __nv_bfloat162 H2; H2.x = ha; H2.y = hb;
    __nv_bfloat162 L2; L2.x = la; L2.y = lb;
    lo = *(uint32_t*)&L2;
    return *(uint32_t*)&H2;
}

// ============================================================
// FUSED gemm1+gemm2. Per CTA: 64 points x full O1=256.
// 256 threads = 8 warps (2M x 4N), warp tile 32(M) x 64(N).
// B operands come straight from fragment-packed global (L1/L2 resident):
//   stage 1: one sync per K-chunk (A ping-pong staging only)
//   stage 2: ZERO syncs in the mainloop (h1 smem is read-only)
// smem 88KB -> 2 CTAs/SM.
// ============================================================
#define FSLD 40
#define H1P  264
#define OTP  68
#define OF_H1HI 0
#define OF_H1LO 33792
#define OF_ABUF 67584        // A ping-pong: hi0,lo0,hi1,lo1 (4 x 5120B)
#define OF_OUTT 0            // aliases h1 (dead at epilogue 2)
#define FSM_BYTES 88064

__global__ void __launch_bounds__(256, 2) fused12_kernel(float* __restrict__ out) {
    extern __shared__ __align__(16) char fsm[];
    __nv_bfloat16* h1hi = (__nv_bfloat16*)(fsm + OF_H1HI);
    __nv_bfloat16* h1lo = (__nv_bfloat16*)(fsm + OF_H1LO);
    float*         outT = (float*)(fsm + OF_OUTT);

    const int tid = threadIdx.x, lane = tid & 31, wid = tid >> 5;
    const int warpM = wid >> 2, warpN = wid & 3;
    const int b = blockIdx.y;
    const int pt0 = blockIdx.x * 64;

    const uint32_t h1hiB = smem_u32(h1hi), h1loB = smem_u32(h1lo);
    const uint32_t abufB = smem_u32(fsm + OF_ABUF);

    const int lrow = tid >> 2;          // 0..63
    const int lcol = (tid & 3) * 8;

    const uint32_t aRowSel = lane & 15;
    const uint32_t aColSel = (lane >> 4) << 3;

    // ---------------- stage 1: h1 = f1T @ W1b^T  (K=128, 4 chunks) ----------------
    const __nv_bfloat16* Ah = g_f1T_hi + ((size_t)b * N1_ + pt0 + lrow) * C1_ + lcol;
    const __nv_bfloat16* Al = g_f1T_lo + ((size_t)b * N1_ + pt0 + lrow) * C1_ + lcol;

    float acc[2][8][4];
    #pragma unroll
    for (int i = 0; i < 2; i++)
        #pragma unroll
        for (int j = 0; j < 8; j++)
            #pragma unroll
            for (int k = 0; k < 4; k++) acc[i][j][k] = 0.f;

    uint4 rA0 = *(const uint4*)Ah;
    uint4 rA1 = *(const uint4*)Al;

    for (int kc = 0; kc < 4; kc++) {
        // stage A chunk into ping-pong buffer (hi,lo) -- buffers at
        // abuf + (kc&1)*10240 (+0 hi, +5120 lo)
        uint32_t bufO = (kc & 1) * 10240u;
        *(uint4*)(fsm + OF_ABUF + bufO + (lrow * FSLD + lcol) * 2) = rA0;
        *(uint4*)(fsm + OF_ABUF + bufO + 5120 + (lrow * FSLD + lcol) * 2) = rA1;

        int nk = (kc < 3) ? (kc + 1) * 32 : 0;
        rA0 = *(const uint4*)(Ah + nk);
        rA1 = *(const uint4*)(Al + nk);

        __syncthreads();   // single sync: buffer kc visible; laggards read other buffer

        #pragma unroll
        for (int ks = 0; ks < 2; ks++) {
            // B fragments direct from packed global
            uint4 fh[4], fl[4];
            #pragma unroll
            for (int nj = 0; nj < 4; nj++) {
                size_t o = ((((size_t)kc * 2 + ks) * 4 + warpN) * 4 + nj) * 32 + lane;
                fh[nj] = g_W1bp_hi[o];
                fl[nj] = g_W1bp_lo[o];
            }
            uint32_t ah[2][4], al[2][4];
            #pragma unroll
            for (int mi = 0; mi < 2; mi++) {
                uint32_t off = bufO + ((warpM * 32 + mi * 16 + aRowSel) * FSLD + ks * 16 + aColSel) * 2;
                ldsm4(ah[mi], abufB + off);
                ldsm4(al[mi], abufB + 5120 + off);
            }
            #pragma unroll
            for (int nj = 0; nj < 4; nj++) {
                const uint32_t* BH = (const uint32_t*)&fh[nj];
                const uint32_t* BL = (const uint32_t*)&fl[nj];
                #pragma unroll
                for (int mi = 0; mi < 2; mi++)
                    #pragma unroll
                    for (int sub = 0; sub < 2; sub++) {
                        int ni = nj * 2 + sub;
                        uint32_t b0 = BH[sub * 2], b1 = BH[sub * 2 + 1];
                        uint32_t c0_ = BL[sub * 2], c1_ = BL[sub * 2 + 1];
                        mma16816(acc[mi][ni], ah[mi], b0, b1);
                        mma16816(acc[mi][ni], ah[mi], c0_, c1_);
                        mma16816(acc[mi][ni], al[mi], b0, b1);
                    }
            }
        }
    }
    __syncthreads();   // all warps done with A buffers (h1 region reused next)

    // ---------------- epilogue 1: gather + bias + relu -> h1 smem ----------------
    {
        const int r0 = lane >> 2;
        const int c0 = (lane & 3) * 2;
        const int*   IX = g_idx + (size_t)b * N1_ * 3;
        const float* WG = g_wgt + (size_t)b * N1_ * 3;
        const float* PT = g_PT + (size_t)b * N2_ * O1_;
        #pragma unroll
        for (int mi = 0; mi < 2; mi++)
            #pragma unroll
            for (int h = 0; h < 2; h++) {
                int gmL = warpM * 32 + mi * 16 + r0 + h * 8;
                int n = pt0 + gmL;
                int i0 = IX[n * 3], i1 = IX[n * 3 + 1], i2 = IX[n * 3 + 2];
                float w0 = WG[n * 3], w1 = WG[n * 3 + 1], w2 = WG[n * 3 + 2];
                #pragma unroll
                for (int ni = 0; ni < 8; ni++) {
                    int gn = warpN * 64 + ni * 8 + c0;
                    float2 p0 = *(const float2*)&PT[(size_t)i0 * O1_ + gn];
                    float2 p1 = *(const float2*)&PT[(size_t)i1 * O1_ + gn];
                    float2 p2 = *(const float2*)&PT[(size_t)i2 * O1_ + gn];
                    float2 bs = *(const float2*)&g_b1eff[gn];
                    float v0 = acc[mi][ni][h * 2 + 0] + bs.x + w0 * p0.x + w1 * p1.x + w2 * p2.x;
                    float v1 = acc[mi][ni][h * 2 + 1] + bs.y + w0 * p0.y + w1 * p1.y + w2 * p2.y;
                    v0 = fmaxf(v0, 0.f); v1 = fmaxf(v1, 0.f);
                    uint32_t lo, hi = splitpack(v0, v1, lo);
                    *(uint32_t*)&h1hi[gmL * H1P + gn] = hi;
                    *(uint32_t*)&h1lo[gmL * H1P + gn] = lo;
                }
            }
    }
    __syncthreads();   // h1 complete & visible

    // ---------------- stage 2: out = relu(h1 @ W2^T + b2)  (K=256, NO syncs) ----------------
    float acc2[2][8][4];
    #pragma unroll
    for (int i = 0; i < 2; i++)
        #pragma unroll
        for (int j = 0; j < 8; j++)
            #pragma unroll
            for (int k = 0; k < 4; k++) acc2[i][j][k] = 0.f;

    for (int kc = 0; kc < 8; kc++) {
        #pragma unroll
        for (int ks = 0; ks < 2; ks++) {
            uint4 fh[4], fl[4];
            #pragma unroll
            for (int nj = 0; nj < 4; nj++) {
                size_t o = ((((size_t)kc * 2 + ks) * 4 + warpN) * 4 + nj) * 32 + lane;
                fh[nj] = g_W2p_hi[o];
                fl[nj] = g_W2p_lo[o];
            }
            uint32_t ah[2][4], al[2][4];
            #pragma unroll
            for (int mi = 0; mi < 2; mi++) {
                uint32_t off = ((warpM * 32 + mi * 16 + aRowSel) * H1P + kc * 32 + ks * 16 + aColSel) * 2;
                ldsm4(ah[mi], h1hiB + off);
                ldsm4(al[mi], h1loB + off);
            }
            #pragma unroll
            for (int nj = 0; nj < 4; nj++) {
                const uint32_t* BH = (const uint32_t*)&fh[nj];
                const uint32_t* BL = (const uint32_t*)&fl[nj];
                #pragma unroll
                for (int mi = 0; mi < 2; mi++)
                    #pragma unroll
                    for (int sub = 0; sub < 2; sub++) {
                        int ni = nj * 2 + sub;
                        uint32_t b0 = BH[sub * 2], b1 = BH[sub * 2 + 1];
                        uint32_t c0_ = BL[sub * 2], c1_ = BL[sub * 2 + 1];
                        mma16816(acc2[mi][ni], ah[mi], b0, b1);
                        mma16816(acc2[mi][ni], ah[mi], c0_, c1_);
                        mma16816(acc2[mi][ni], al[mi], b0, b1);
                    }
            }
        }
    }
    __syncthreads();   // all h1 reads done before outT overwrites it

    // ---------------- epilogue 2: transpose via smem, coalesced store ----------------
    {
        const int r0 = lane >> 2;
        const int c0 = (lane & 3) * 2;
        #pragma unroll
        for (int mi = 0; mi < 2; mi++)
            #pragma unroll
            for (int h = 0; h < 2; h++) {
                int gmL = warpM * 32 + mi * 16 + r0 + h * 8;
                #pragma unroll
                for (int ni = 0; ni < 8; ni++) {
                    int gn = warpN * 64 + ni * 8 + c0;
                    float2 bs = *(const float2*)&g_b2eff[gn];
                    outT[(size_t)gn * OTP + gmL]       = fmaxf(acc2[mi][ni][h * 2 + 0] + bs.x, 0.f);
                    outT[(size_t)(gn + 1) * OTP + gmL] = fmaxf(acc2[mi][ni][h * 2 + 1] + bs.y, 0.f);
                }
            }
    }
    __syncthreads();

    float* dst = out + (size_t)b * O2_ * N1_ + pt0;
    for (int i = tid; i < 256 * 16; i += 256) {
        int o2 = i >> 4;
        int c = (i & 15) << 2;
        uint4 v = *(uint4*)&outT[o2 * OTP + c];
        *(uint4*)(dst + (size_t)o2 * N1_ + c) = v;
    }
}

// ============================================================
// gemmP: PT[b][n2][o1] = (f2T @ W1a^T)   (verified core, unchanged)
// ============================================================
__global__ void __launch_bounds__(256, 2) gemmP_kernel() {
    __shared__ __align__(16) __nv_bfloat16 sAhi[64][FSLD],  sAlo[64][FSLD];
    __shared__ __align__(16) __nv_bfloat16 sBhi[128][FSLD], sBlo[128][FSLD];

    const int tid = threadIdx.x, lane = tid & 31, wid = tid >> 5;
    const int warpM = wid >> 2, warpN = wid & 3;
    const int b = blockIdx.z;
    const int Mbase = blockIdx.x * 64, Nbase = blockIdx.y * 128;

    float acc[2][4][4];
    #pragma unroll
    for (int i = 0; i < 2; i++)
        #pragma unroll
        for (int j = 0; j < 4; j++)
            #pragma unroll
            for (int k = 0; k < 4; k++) acc[i][j][k] = 0.f;

    const int lrow = tid >> 2;
    const int lcol = (tid & 3) * 8;

    const __nv_bfloat16* pAhi = g_f2T_hi + ((size_t)b * N2_ + Mbase + lrow) * C2_ + lcol;
    const __nv_bfloat16* pAlo = g_f2T_lo + ((size_t)b * N2_ + Mbase + lrow) * C2_ + lcol;
    const __nv_bfloat16* pBhi0 = g_W1a_hi + (size_t)(Nbase + lrow) * C2_ + lcol;
    const __nv_bfloat16* pBlo0 = g_W1a_lo + (size_t)(Nbase + lrow) * C2_ + lcol;
    const __nv_bfloat16* pBhi1 = g_W1a_hi + (size_t)(Nbase + lrow + 64) * C2_ + lcol;
    const __nv_bfloat16* pBlo1 = g_W1a_lo + (size_t)(Nbase + lrow + 64) * C2_ + lcol;

    const uint32_t aRowA = warpM * 32 + (lane & 15);
    const uint32_t aColA = (lane >> 4) << 3;
    const uint32_t bRowB = warpN * 32 + ((lane >> 4) << 3) + (lane & 7);
    const uint32_t bColB = ((lane >> 3) & 1) << 3;
    const uint32_t sAhiB = smem_u32(&sAhi[0][0]), sAloB = smem_u32(&sAlo[0][0]);
    const uint32_t sBhiB = smem_u32(&sBhi[0][0]), sBloB = smem_u32(&sBlo[0][0]);

    uint4 rA0 = *(const uint4*)pAhi,  rA1 = *(const uint4*)pAlo;
    uint4 rBh0 = *(const uint4*)pBhi0, rBh1 = *(const uint4*)pBhi1;
    uint4 rBl0 = *(const uint4*)pBlo0, rBl1 = *(const uint4*)pBlo1;

    for (int kb = 0; kb < C2_; kb += 32) {
        *(uint4*)&sAhi[lrow][lcol] = rA0;
        *(uint4*)&sAlo[lrow][lcol] = rA1;
        *(uint4*)&sBhi[lrow][lcol] = rBh0;
        *(uint4*)&sBhi[lrow + 64][lcol] = rBh1;
        *(uint4*)&sBlo[lrow][lcol] = rBl0;
        *(uint4*)&sBlo[lrow + 64][lcol] = rBl1;
        __syncthreads();

        int nk = (kb + 32 < C2_) ? kb + 32 : 0;
        rA0 = *(const uint4*)(pAhi + nk);  rA1 = *(const uint4*)(pAlo + nk);
        rBh0 = *(const uint4*)(pBhi0 + nk); rBh1 = *(const uint4*)(pBhi1 + nk);
        rBl0 = *(const uint4*)(pBlo0 + nk); rBl1 = *(const uint4*)(pBlo1 + nk);

        #pragma unroll
        for (int ks = 0; ks < 2; ks++) {
            uint32_t ah[2][4], al[2][4], bh[2][4], bl[2][4];
            #pragma unroll
            for (int mi = 0; mi < 2; mi++) {
                uint32_t off = ((aRowA + mi * 16) * FSLD + ks * 16 + aColA) * 2;
                ldsm4(ah[mi], sAhiB + off);
                ldsm4(al[mi], sAloB + off);
            }
            #pragma unroll
            for (int nj = 0; nj < 2; nj++) {
                uint32_t off = ((bRowB + nj * 16) * FSLD + ks * 16 + bColB) * 2;
                ldsm4(bh[nj], sBhiB + off);
                ldsm4(bl[nj], sBloB + off);
            }
            #pragma unroll
            for (int mi = 0; mi < 2; mi++)
                #pragma unroll
                for (int ni = 0; ni < 4; ni++) {
                    const uint32_t* BH = bh[ni >> 1];
                    const uint32_t* BL = bl[ni >> 1];
                    uint32_t b0 = BH[(ni & 1) * 2], b1 = BH[(ni & 1) * 2 + 1];
                    uint32_t c0_ = BL[(ni & 1) * 2], c1_ = BL[(ni & 1) * 2 + 1];
                    mma16816(acc[mi][ni], ah[mi], b0, b1);
                    mma16816(acc[mi][ni], ah[mi], c0_, c1_);
                    mma16816(acc[mi][ni], al[mi], b0, b1);
                }
        }
        __syncthreads();
    }

    const int r0 = lane >> 2;
    const int c0 = (lane & 3) * 2;
    float* outP = g_PT + (size_t)b * N2_ * O1_;
    #pragma unroll
    for (int mi = 0; mi < 2; mi++)
        #pragma unroll
        for (int h = 0; h < 2; h++) {
            int gm = Mbase + warpM * 32 + mi * 16 + r0 + h * 8;
            #pragma unroll
            for (int ni = 0; ni < 4; ni++) {
                int gn = Nbase + warpN * 32 + ni * 8 + c0;
                *(float2*)&outP[(size_t)gm * O1_ + gn] =
                    make_float2(acc[mi][ni][h * 2], acc[mi][ni][h * 2 + 1]);
            }
        }
}

// ============================================================
// prep: fold BN into W/b, split weights into bf16 hi/lo
// ============================================================
__global__ void prep_kernel(const float* __restrict__ W1, const float* __restrict__ b1,
                            const float* __restrict__ g1, const float* __restrict__ be1,
                            const float* __restrict__ W2, const float* __restrict__ b2,
                            const float* __restrict__ g2, const float* __restrict__ be2) {
    const float rs = 0.99999500003749969f;  // 1/sqrt(1+1e-5)
    int t = blockIdx.x * blockDim.x + threadIdx.x;
    int nt = gridDim.x * blockDim.x;
    for (int i = t; i < O1_ * C2_; i += nt) {
        int o = i / C2_;
        float w = W1[o * (C1_ + C2_) + (i % C2_)] * g1[o] * rs;
        __nv_bfloat16 hi = __float2bfloat16(w);
        g_W1a_hi[i] = hi;
        g_W1a_lo[i] = __float2bfloat16(w - __bfloat162float(hi));
    }
    for (int i = t; i < O1_ * C1_; i += nt) {
        int o = i / C1_;
        float w = W1[o * (C1_ + C2_) + C2_ + (i % C1_)] * g1[o] * rs;
        __nv_bfloat16 hi = __float2bfloat16(w);
        g_W1b_hi[i] = hi;
        g_W1b_lo[i] = __float2bfloat16(w - __bfloat162float(hi));
    }
    for (int i = t; i < O2_ * O1_; i += nt) {
        int o = i / O1_;
        float w = W2[i] * g2[o] * rs;
        __nv_bfloat16 hi = __float2bfloat16(w);
        g_W2_hi[i] = hi;
        g_W2_lo[i] = __float2bfloat16(w - __bfloat162float(hi));
    }
    for (int i = t; i < O1_; i += nt) g_b1eff[i] = g1[i] * rs * b1[i] + be1[i];
    for (int i = t; i < O2_; i += nt) g_b2eff[i] = g2[i] * rs * b2[i] + be2[i];
}

// ============================================================
// pack: rearrange W1b / W2 (hi,lo) into ldmatrix-fragment order.
// reg j of lane l for tile (n0,k0):
//   n = n0 + (j>=2 ? 8:0) + l/4 ; k = k0 + (j&1 ? 8:0) + (l&3)*2
// ============================================================
__device__ __forceinline__ uint32_t bf2pack(const __nv_bfloat16* W, int ld, int n, int k) {
    __nv_bfloat162 v;
    v.x = W[(size_t)n * ld + k];
    v.y = W[(size_t)n * ld + k + 1];
    return *(uint32_t*)&v;
}

__global__ void pack_kernel() {
    int t = blockIdx.x * blockDim.x + threadIdx.x;
    int nt = gridDim.x * blockDim.x;
    // W2: 8*2*4*4*32 = 8192 entries
    for (int i = t; i < 8192; i += nt) {
        int lane = i & 31, nj = (i >> 5) & 3, wN = (i >> 7) & 3, ks = (i >> 9) & 1, kc = i >> 10;
        int n0 = wN * 64 + nj * 16, k0 = kc * 32 + ks * 16;
        uint4 h, l;
        uint32_t* hp = (uint32_t*)&h;
        uint32_t* lp = (uint32_t*)&l;
        #pragma unroll
        for (int j = 0; j < 4; j++) {
            int n = n0 + ((j >> 1) << 3) + (lane >> 2);
            int k = k0 + ((j & 1) << 3) + (lane & 3) * 2;
            hp[j] = bf2pack(g_W2_hi, O1_, n, k);
            lp[j] = bf2pack(g_W2_lo, O1_, n, k);
        }
        g_W2p_hi[i] = h;
        g_W2p_lo[i] = l;
    }
    // W1b: 4*2*4*4*32 = 4096 entries
    for (int i = t; i < 4096; i += nt) {
        int lane = i & 31, nj = (i >> 5) & 3, wN = (i >> 7) & 3, ks = (i >> 9) & 1, kc = i >> 10;
        int n0 = wN * 64 + nj * 16, k0 = kc * 32 + ks * 16;
        uint4 h, l;
        uint32_t* hp = (uint32_t*)&h;
        uint32_t* lp = (uint32_t*)&l;
        #pragma unroll
        for (int j = 0; j < 4; j++) {
            int n = n0 + ((j >> 1) << 3) + (lane >> 2);
            int k = k0 + ((j & 1) << 3) + (lane & 3) * 2;
            hp[j] = bf2pack(g_W1b_hi, C1_, n, k);
            lp[j] = bf2pack(g_W1b_lo, C1_, n, k);
        }
        g_W1bp_hi[i] = h;
        g_W1bp_lo[i] = l;
    }
}

// ============================================================
// kNN: R6-proven smem float4 version (1 point/thread)
// ============================================================
__global__ void __launch_bounds__(256) knn_kernel(const float* __restrict__ xyz1,
                                                  const float* __restrict__ xyz2) {
    __shared__ __align__(16) float4 s2[N2_];
    int b = blockIdx.y;
    const float* q = xyz2 + (size_t)b * N2_ * 3;
    for (int i = threadIdx.x; i < N2_; i += 256) {
        float ax = q[i * 3 + 0], ay = q[i * 3 + 1], az = q[i * 3 + 2];
        s2[i] = make_float4(ax, ay, az, ax * ax + ay * ay + az * az);
    }
    __syncthreads();

    int p = blockIdx.x * 256 + threadIdx.x;
    const float* pp = xyz1 + ((size_t)b * N1_ + p) * 3;
    float x = pp[0], y = pp[1], z = pp[2];
    float p2 = x * x + y * y + z * z;

    float d0 = 3.4e38f, d1 = 3.4e38f, d2 = 3.4e38f;
    int   j0 = 0, j1 = 0, j2 = 0;
    #pragma unroll 4
    for (int m = 0; m < N2_; m++) {
        float4 v = s2[m];
        float dot = x * v.x + y * v.y + z * v.z;
        float dd  = (p2 + v.w) - 2.0f * dot;
        if (dd < d2) {
            if (dd < d1) {
                d2 = d1; j2 = j1;
                if (dd < d0) { d1 = d0; j1 = j0; d0 = dd; j0 = m; }
                else         { d1 = dd; j1 = m; }
            } else { d2 = dd; j2 = m; }
        }
    }
    float r0 = sqrtf(fmaxf(d0, 0.f));
    float r1 = sqrtf(fmaxf(d1, 0.f));
    float r2 = sqrtf(fmaxf(d2, 0.f));
    float w0 = 1.0f / fmaxf(r0, 1e-8f);
    float w1 = 1.0f / fmaxf(r1, 1e-8f);
    float w2 = 1.0f / fmaxf(r2, 1e-8f);
    float inv = 1.0f / (w0 + w1 + w2);

    size_t base = ((size_t)b * N1_ + p) * 3;
    g_idx[base + 0] = j0; g_idx[base + 1] = j1; g_idx[base + 2] = j2;
    g_wgt[base + 0] = w0 * inv; g_wgt[base + 1] = w1 * inv; g_wgt[base + 2] = w2 * inv;
}

// ============================================================
// tsplit_both: transpose + split feats1 AND feats2 (4.2KB smem)
// ============================================================
#define TS1_BLKS  ((N1_ / 32) * (C1_ / 32) * B_)      // 8192
#define TS2_BLKS  ((N2_ / 32) * (C2_ / 32) * B_)      // 4096

__device__ __forceinline__ void tsplit_tile(int n_t, int c_t, int b,
                                            const float* __restrict__ src,
                                            __nv_bfloat16* __restrict__ dhi,
                                            __nv_bfloat16* __restrict__ dlo,
                                            int C, int Np, float (*t)[33]) {
    int n0 = n_t * 32, c0 = c_t * 32;
    int tx = threadIdx.x & 31, ty = threadIdx.x >> 5;
    #pragma unroll
    for (int r = 0; r < 4; r++) {
        int c = c0 + ty + r * 8;
        t[ty + r * 8][tx] = src[((size_t)b * C + c) * Np + n0 + tx];
    }
    __syncthreads();
    #pragma unroll
    for (int r = 0; r < 4; r++) {
        int n = n0 + ty + r * 8;
        int c = c0 + tx;
        float v = t[tx][ty + r * 8];
        __nv_bfloat16 hi = __float2bfloat16(v);
        size_t o = ((size_t)b * Np + n) * C + c;
        dhi[o] = hi;
        dlo[o] = __float2bfloat16(v - __bfloat162float(hi));
    }
}

__global__ void __launch_bounds__(256) tsplit_kernel(const float* __restrict__ feats1,
                                                     const float* __restrict__ feats2) {
    __shared__ float t[32][33];
    int bid = blockIdx.x;
    if (bid < TS1_BLKS) {
        int n_t = bid & 255, c_t = (bid >> 8) & 3, b = bid >> 10;
        tsplit_tile(n_t, c_t, b, feats1, g_f1T_hi, g_f1T_lo, C1_, N1_, t);
    } else {
        bid -= TS1_BLKS;
        int n_t = bid & 63, c_t = (bid >> 6) & 7, b = bid >> 9;
        tsplit_tile(n_t, c_t, b, feats2, g_f2T_hi, g_f2T_lo, C2_, N2_, t);
    }
}

// ============================================================
extern "C" void kernel_launch(void* const* d_in, const int* in_sizes, int n_in,
                              void* d_out, int out_size) {
    const float* xyz1   = (const float*)d_in[0];
    const float* xyz2   = (const float*)d_in[1];
    const float* feats1 = (const float*)d_in[2];
    const float* feats2 = (const float*)d_in[3];
    const float* W1     = (const float*)d_in[4];
    const float* b1     = (const float*)d_in[5];
    const float* g1     = (const float*)d_in[6];
    const float* be1    = (const float*)d_in[7];
    const float* W2     = (const float*)d_in[8];
    const float* b2     = (const float*)d_in[9];
    const float* g2     = (const float*)d_in[10];
    const float* be2    = (const float*)d_in[11];
    float* out = (float*)d_out;

    cudaFuncSetAttribute(fused12_kernel, cudaFuncAttributeMaxDynamicSharedMemorySize, FSM_BYTES);

    prep_kernel<<<64, 256>>>(W1, b1, g1, be1, W2, b2, g2, be2);       // idx 0
    pack_kernel<<<32, 256>>>();                                       // idx 1
    knn_kernel<<<dim3(N1_ / 256, B_), 256>>>(xyz1, xyz2);             // idx 2
    tsplit_kernel<<<TS1_BLKS + TS2_BLKS, 256>>>(feats1, feats2);      // idx 3
    gemmP_kernel<<<dim3(N2_ / 64, O1_ / 128, B_), 256>>>();           // idx 4
    fused12_kernel<<<dim3(N1_ / 64, B_), 256, FSM_BYTES>>>(out);      // idx 5 -> ncu (-s 5 -c 1)
}